// round 1
// baseline (speedup 1.0000x reference)
#include <cuda_runtime.h>
#include <cstdint>

// Problem constants
#define Bb     8
#define Ll     4096
#define Dd     1024
#define Hh     16
#define BLK    4
#define HDIM   64
#define MTOT   (Bb*Ll)        // 32768
#define NQKV   (3*Dd)         // 3072

// Scratch (no cudaMalloc allowed): 402MB + 134MB
__device__ float g_qkv[100663296];  // 32768 * 3072
__device__ float g_o[33554432];     // 32768 * 1024

// ---------------------------------------------------------------------------
// TF32 helpers
// ---------------------------------------------------------------------------
__device__ __forceinline__ uint32_t f2tf32(float f) {
    uint32_t r;
    asm("cvt.rna.tf32.f32 %0, %1;" : "=r"(r) : "f"(f));
    return r;
}

__device__ __forceinline__ void mma_tf32(float c[4], const uint32_t a[4], const uint32_t b[2]) {
    asm volatile(
        "mma.sync.aligned.m16n8k8.row.col.f32.tf32.tf32.f32 "
        "{%0,%1,%2,%3}, {%4,%5,%6,%7}, {%8,%9}, {%0,%1,%2,%3};\n"
        : "+f"(c[0]), "+f"(c[1]), "+f"(c[2]), "+f"(c[3])
        : "r"(a[0]), "r"(a[1]), "r"(a[2]), "r"(a[3]),
          "r"(b[0]), "r"(b[1]));
}

// ---------------------------------------------------------------------------
// TF32 GEMM: C[M,N] = A[M,K] @ B[K,N] + bias[N]
// CTA tile 128x64, BK=32, 256 threads (8 warps, 4x2 of 32x32 warp tiles)
// Requires: M%128==0, N%64==0, K%32==0 (holds for all our shapes)
// ---------------------------------------------------------------------------
#define BM 128
#define BN 64
#define BK 32

__global__ __launch_bounds__(256)
void gemm_tf32_kernel(const float* __restrict__ A,
                      const float* __restrict__ Bm,
                      const float* __restrict__ bias,
                      float* __restrict__ C,
                      int M, int N, int K)
{
    __shared__ uint32_t As[BM][BK + 1];   // +1 pad: break bank conflicts
    __shared__ uint32_t Bs[BK][BN + 1];

    const int tid  = threadIdx.x;
    const int warp = tid >> 5;
    const int lane = tid & 31;
    const int warpM = warp >> 1;   // 0..3
    const int warpN = warp & 1;    // 0..1

    const int blockRow = blockIdx.y * BM;
    const int blockCol = blockIdx.x * BN;

    float acc[2][4][4];
    #pragma unroll
    for (int mt = 0; mt < 2; ++mt)
        #pragma unroll
        for (int nt = 0; nt < 4; ++nt)
            #pragma unroll
            for (int r = 0; r < 4; ++r) acc[mt][nt][r] = 0.0f;

    // Staging assignments
    const int ar  = tid >> 3;         // 0..31 (row within 32-row pass)
    const int ac4 = (tid & 7) * 4;    // col 0..28 step 4
    const int br  = tid >> 4;         // 0..15
    const int bc4 = (tid & 15) * 4;   // 0..60

    const float* Aptr = A + (size_t)(blockRow + ar) * K + ac4;
    const float* Bptr = Bm + (size_t)br * N + blockCol + bc4;

    const int laneRow = lane >> 2;    // 0..7
    const int laneCol = lane & 3;     // 0..3

    for (int k0 = 0; k0 < K; k0 += BK) {
        // ---- stage A tile (128x32) ----
        #pragma unroll
        for (int i = 0; i < 4; ++i) {
            float4 v = *(const float4*)(Aptr + (size_t)(i * 32) * K + k0);
            uint32_t* dst = &As[ar + i * 32][ac4];
            dst[0] = f2tf32(v.x); dst[1] = f2tf32(v.y);
            dst[2] = f2tf32(v.z); dst[3] = f2tf32(v.w);
        }
        // ---- stage B tile (32x64) ----
        #pragma unroll
        for (int i = 0; i < 2; ++i) {
            float4 v = *(const float4*)(Bptr + (size_t)(k0 + i * 16) * N);
            uint32_t* dst = &Bs[br + i * 16][bc4];
            dst[0] = f2tf32(v.x); dst[1] = f2tf32(v.y);
            dst[2] = f2tf32(v.z); dst[3] = f2tf32(v.w);
        }
        __syncthreads();

        // ---- 4 k-steps of 8 ----
        #pragma unroll
        for (int kk = 0; kk < 4; ++kk) {
            uint32_t af[2][4];
            #pragma unroll
            for (int mt = 0; mt < 2; ++mt) {
                int r = warpM * 32 + mt * 16 + laneRow;
                int c = kk * 8 + laneCol;
                af[mt][0] = As[r][c];
                af[mt][1] = As[r + 8][c];
                af[mt][2] = As[r][c + 4];
                af[mt][3] = As[r + 8][c + 4];
            }
            uint32_t bf[4][2];
            #pragma unroll
            for (int nt = 0; nt < 4; ++nt) {
                int n0 = warpN * 32 + nt * 8 + laneRow;
                int kb = kk * 8 + laneCol;
                bf[nt][0] = Bs[kb][n0];
                bf[nt][1] = Bs[kb + 4][n0];
            }
            #pragma unroll
            for (int mt = 0; mt < 2; ++mt)
                #pragma unroll
                for (int nt = 0; nt < 4; ++nt)
                    mma_tf32(acc[mt][nt], af[mt], bf[nt]);
        }
        __syncthreads();
    }

    // ---- epilogue: += bias, write ----
    #pragma unroll
    for (int mt = 0; mt < 2; ++mt) {
        #pragma unroll
        for (int nt = 0; nt < 4; ++nt) {
            int row = blockRow + warpM * 32 + mt * 16 + laneRow;
            int col = blockCol + warpN * 32 + nt * 8 + laneCol * 2;
            float bv0 = bias[col];
            float bv1 = bias[col + 1];
            C[(size_t)row * N + col]           = acc[mt][nt][0] + bv0;
            C[(size_t)row * N + col + 1]       = acc[mt][nt][1] + bv1;
            C[(size_t)(row + 8) * N + col]     = acc[mt][nt][2] + bv0;
            C[(size_t)(row + 8) * N + col + 1] = acc[mt][nt][3] + bv1;
        }
    }
}

// ---------------------------------------------------------------------------
// Block attention: one warp per (b, h, block). BS=4, d=64.
// qkv layout: [B, L, 3*D], per (l): H chunks of 192 = [q(64) | k(64) | v(64)]
// o layout:   [B, L, D], o[b, l, h*64 + dd]
// ---------------------------------------------------------------------------
__global__ __launch_bounds__(256)
void block_attn_kernel(const float* __restrict__ qkv, float* __restrict__ o)
{
    const int gwarp = (blockIdx.x * blockDim.x + threadIdx.x) >> 5;
    const int lane  = threadIdx.x & 31;

    const int nb = gwarp & 1023;        // block index within (b,h): L/BS = 1024
    const int bh = gwarp >> 10;
    const int h  = bh & 15;
    const int b  = bh >> 4;
    const int l0 = nb * BLK;

    const size_t rowBase = ((size_t)(b * Ll + l0)) * NQKV + h * 192;

    float2 q[4], k[4], v[4];
    #pragma unroll
    for (int i = 0; i < 4; ++i) {
        const float* p = qkv + rowBase + (size_t)i * NQKV + 2 * lane;
        q[i] = *(const float2*)(p);
        k[i] = *(const float2*)(p + 64);
        v[i] = *(const float2*)(p + 128);
    }

    // 4x4 score matrix, reduced over d=64 (2 dims per lane -> butterfly)
    float s[4][4];
    #pragma unroll
    for (int i = 0; i < 4; ++i)
        #pragma unroll
        for (int j = 0; j < 4; ++j)
            s[i][j] = fmaf(q[i].y, k[j].y, q[i].x * k[j].x);

    #pragma unroll
    for (int i = 0; i < 4; ++i)
        #pragma unroll
        for (int j = 0; j < 4; ++j)
            #pragma unroll
            for (int off = 16; off > 0; off >>= 1)
                s[i][j] += __shfl_xor_sync(0xffffffffu, s[i][j], off);

    const float scale = 0.125f;  // 64^-0.5
    float2 outv[4];
    #pragma unroll
    for (int i = 0; i < 4; ++i) {
        float t0 = s[i][0] * scale, t1 = s[i][1] * scale;
        float t2 = s[i][2] * scale, t3 = s[i][3] * scale;
        float m = fmaxf(fmaxf(t0, t1), fmaxf(t2, t3));
        float e0 = __expf(t0 - m), e1 = __expf(t1 - m);
        float e2 = __expf(t2 - m), e3 = __expf(t3 - m);
        float inv = 1.0f / (e0 + e1 + e2 + e3);
        float p0 = e0 * inv, p1 = e1 * inv, p2 = e2 * inv, p3 = e3 * inv;
        float ox = p0 * v[0].x; ox = fmaf(p1, v[1].x, ox);
        ox = fmaf(p2, v[2].x, ox); ox = fmaf(p3, v[3].x, ox);
        float oy = p0 * v[0].y; oy = fmaf(p1, v[1].y, oy);
        oy = fmaf(p2, v[2].y, oy); oy = fmaf(p3, v[3].y, oy);
        outv[i].x = ox; outv[i].y = oy;
    }

    const size_t obase = ((size_t)(b * Ll + l0)) * Dd + h * HDIM + 2 * lane;
    #pragma unroll
    for (int i = 0; i < 4; ++i)
        *(float2*)(o + obase + (size_t)i * Dd) = outv[i];
}

// ---------------------------------------------------------------------------
// Launch: qkv GEMM -> block attention -> proj GEMM
// ---------------------------------------------------------------------------
extern "C" void kernel_launch(void* const* d_in, const int* in_sizes, int n_in,
                              void* d_out, int out_size)
{
    const float* x     = (const float*)d_in[0];
    const float* Wqkv  = (const float*)d_in[1];
    const float* bqkv  = (const float*)d_in[2];
    const float* Wproj = (const float*)d_in[3];
    const float* bproj = (const float*)d_in[4];
    float* out = (float*)d_out;

    float* qkv = nullptr;
    float* ob  = nullptr;
    cudaGetSymbolAddress((void**)&qkv, g_qkv);
    cudaGetSymbolAddress((void**)&ob, g_o);

    // 1) qkv = x @ W_qkv + b_qkv   (32768 x 3072 x 1024)
    {
        dim3 grid(NQKV / BN, MTOT / BM);
        gemm_tf32_kernel<<<grid, 256>>>(x, Wqkv, bqkv, qkv, MTOT, NQKV, Dd);
    }

    // 2) block attention: 8*16*1024 = 131072 warps, 8 warps/CTA
    {
        int nwarps = Bb * Hh * (Ll / BLK);
        block_attn_kernel<<<nwarps / 8, 256>>>(qkv, ob);
    }

    // 3) out = o @ W_proj + b_proj  (32768 x 1024 x 1024)
    {
        dim3 grid(Dd / BN, MTOT / BM);
        gemm_tf32_kernel<<<grid, 256>>>(ob, Wproj, bproj, out, MTOT, Dd, Dd);
    }
}

// round 3
// speedup vs baseline: 2.2079x; 2.2079x over previous
#include <cuda_runtime.h>
#include <cstdint>

// Problem constants
#define Bb     8
#define Ll     4096
#define Dd     1024
#define Hh     16
#define BLK    4
#define HDIM   64
#define MTOT   (Bb*Ll)        // 32768
#define NQKV   (3*Dd)         // 3072

// Scratch (no cudaMalloc allowed)
__device__ float g_qkv[100663296];  // 32768 * 3072
__device__ float g_o[33554432];     // 32768 * 1024

// ---------------------------------------------------------------------------
// helpers
// ---------------------------------------------------------------------------
__device__ __forceinline__ uint32_t smem_u32(const void* p) {
    uint32_t a;
    asm("{ .reg .u64 t; cvta.to.shared.u64 t, %1; cvt.u32.u64 %0, t; }" : "=r"(a) : "l"(p));
    return a;
}

__device__ __forceinline__ uint32_t tf32_of_bits(uint32_t u) {
    uint32_t r;
    asm("cvt.rna.tf32.f32 %0, %1;" : "=r"(r) : "f"(__uint_as_float(u)));
    return r;
}

__device__ __forceinline__ void cpasync16(uint32_t dst, const void* src) {
    asm volatile("cp.async.cg.shared.global [%0], [%1], 16;" :: "r"(dst), "l"(src));
}
#define CP_COMMIT() asm volatile("cp.async.commit_group;" ::: "memory")
#define CP_WAIT2()  asm volatile("cp.async.wait_group 2;" ::: "memory")

__device__ __forceinline__ void mma_tf32(float c[4], const uint32_t a[4], const uint32_t b[2]) {
    asm volatile(
        "mma.sync.aligned.m16n8k8.row.col.f32.tf32.tf32.f32 "
        "{%0,%1,%2,%3}, {%4,%5,%6,%7}, {%8,%9}, {%0,%1,%2,%3};\n"
        : "+f"(c[0]), "+f"(c[1]), "+f"(c[2]), "+f"(c[3])
        : "r"(a[0]), "r"(a[1]), "r"(a[2]), "r"(a[3]),
          "r"(b[0]), "r"(b[1]));
}

// ---------------------------------------------------------------------------
// TF32 GEMM via mma.sync, CTA tile 128(M) x 256(N), BK=32, 8 warps of 64x64.
// A smem: K-major 128B rows, SW128 swizzle, loaded via ldmatrix.x4 (tf32-as-2xb16).
// B smem: K-major rows padded to 264 words (bank = 8k+n, conflict-free LDS.32).
// 3-stage cp.async pipeline. Requires M%128==0, N%256==0, K%32==0.
// ---------------------------------------------------------------------------
#define A_STAGE 16384
#define B_ROWB  1056                 // 264 floats
#define B_STAGE (32 * B_ROWB)        // 33792
#define STAGES  3
#define GEMM_SMEM (STAGES * (A_STAGE + B_STAGE))   // 150528

__global__ __launch_bounds__(256, 1)
void gemm_mma_kernel(const float* __restrict__ A, const float* __restrict__ W,
                     const float* __restrict__ bias, float* __restrict__ C,
                     int N, int K)
{
    extern __shared__ char dsm[];
    const uint32_t sbase = smem_u32(dsm);

    uint32_t aSt[STAGES], bSt[STAGES];
#pragma unroll
    for (int s = 0; s < STAGES; ++s) {
        aSt[s] = sbase + s * A_STAGE;
        bSt[s] = sbase + STAGES * A_STAGE + s * B_STAGE;
    }

    const int tid  = threadIdx.x;
    const int wid  = tid >> 5;
    const int lane = tid & 31;
    const int warpM = wid & 1;       // 2 rows of 64
    const int warpN = wid >> 1;      // 4 cols of 64

    const int m0 = blockIdx.y * 128;
    const int n0 = blockIdx.x * 256;

    const float* Ag = A + (size_t)m0 * K;
    const float* Wg = W + n0;
    const int NC = K >> 5;

    float acc[4][8][4];
#pragma unroll
    for (int mt = 0; mt < 4; ++mt)
#pragma unroll
        for (int nt = 0; nt < 8; ++nt)
#pragma unroll
            for (int r = 0; r < 4; ++r) acc[mt][nt][r] = 0.0f;

    // ---- staging lambda: chunk c -> stage s ----
    auto stage = [&](int c, int s) {
        const int k0 = c << 5;
        // A: 128 rows x 32 floats = 1024 16B-chunks
#pragma unroll
        for (int it = 0; it < 4; ++it) {
            int idx = tid + it * 256;
            int m = idx >> 3, k16 = idx & 7;
            cpasync16(aSt[s] + m * 128 + ((k16 ^ (m & 7)) << 4),
                      Ag + (size_t)m * K + k0 + k16 * 4);
        }
        // B: 32 rows x 256 floats = 2048 16B-chunks (padded rows)
#pragma unroll
        for (int it = 0; it < 8; ++it) {
            int idx = tid + it * 256;
            int k = idx >> 6, n16 = idx & 63;
            cpasync16(bSt[s] + k * B_ROWB + n16 * 16,
                      Wg + (size_t)(k0 + k) * N + n16 * 4);
        }
    };

    stage(0, 0); CP_COMMIT();
    stage(1, 1); CP_COMMIT();

    // A ldmatrix address pieces (per lane, per mt/ks)
    const int r8  = lane & 7;
    const int sel = lane >> 3;                 // 0..3 -> mat0..3
    const int rowAdd = r8 + ((sel & 2) << 2);  // +8 rows for mats 2,3
    const int colAdd = sel & 1;                // +1 16B-col for mats 1,3

    for (int c = 0; c < NC; ++c) {
        if (c + 2 < NC) stage(c + 2, (c + 2) % STAGES);
        CP_COMMIT();
        CP_WAIT2();
        __syncthreads();

        const uint32_t aB = aSt[c % STAGES];
        const uint32_t bB = bSt[c % STAGES];

#pragma unroll
        for (int ks = 0; ks < 4; ++ks) {
            // ---- A fragments: 4 m-tiles via ldmatrix.x4 ----
            uint32_t aF[4][4];
#pragma unroll
            for (int mt = 0; mt < 4; ++mt) {
                int row = warpM * 64 + mt * 16 + rowAdd;
                int col16 = 2 * ks + colAdd;
                uint32_t addr = aB + row * 128 + (((col16 ^ (row & 7)) << 4));
                uint32_t r0, r1, r2, r3;
                asm volatile("ldmatrix.sync.aligned.m8n8.x4.shared.b16 {%0,%1,%2,%3}, [%4];"
                             : "=r"(r0), "=r"(r1), "=r"(r2), "=r"(r3) : "r"(addr));
                aF[mt][0] = tf32_of_bits(r0);
                aF[mt][1] = tf32_of_bits(r2);
                aF[mt][2] = tf32_of_bits(r1);
                aF[mt][3] = tf32_of_bits(r3);
            }
            // ---- B fragments: 8 n-tiles, conflict-free LDS.32 ----
            uint32_t bF[8][2];
            const uint32_t bk = bB + (ks * 8 + (lane & 3)) * B_ROWB
                              + (warpN * 64 + (lane >> 2)) * 4;
#pragma unroll
            for (int nt = 0; nt < 8; ++nt) {
                uint32_t u0, u1;
                asm volatile("ld.shared.b32 %0, [%1];" : "=r"(u0) : "r"(bk + nt * 32));
                asm volatile("ld.shared.b32 %0, [%1];" : "=r"(u1) : "r"(bk + nt * 32 + 4 * B_ROWB));
                bF[nt][0] = tf32_of_bits(u0);
                bF[nt][1] = tf32_of_bits(u1);
            }
            // ---- 32 MMAs ----
#pragma unroll
            for (int mt = 0; mt < 4; ++mt)
#pragma unroll
                for (int nt = 0; nt < 8; ++nt)
                    mma_tf32(acc[mt][nt], aF[mt], bF[nt]);
        }
        __syncthreads();
    }

    // ---- epilogue: bias + coalesced-enough STG.64 ----
    const int col0 = n0 + warpN * 64 + 2 * (lane & 3);
    float2 bv[8];
#pragma unroll
    for (int nt = 0; nt < 8; ++nt)
        bv[nt] = *(const float2*)(bias + col0 + nt * 8);

    const int row0 = m0 + warpM * 64 + (lane >> 2);
#pragma unroll
    for (int mt = 0; mt < 4; ++mt) {
        int r = row0 + mt * 16;
#pragma unroll
        for (int nt = 0; nt < 8; ++nt) {
            int cn = col0 + nt * 8;
            float2 v0, v1;
            v0.x = acc[mt][nt][0] + bv[nt].x;
            v0.y = acc[mt][nt][1] + bv[nt].y;
            v1.x = acc[mt][nt][2] + bv[nt].x;
            v1.y = acc[mt][nt][3] + bv[nt].y;
            *(float2*)(C + (size_t)r * N + cn)       = v0;
            *(float2*)(C + (size_t)(r + 8) * N + cn) = v1;
        }
    }
}

// ---------------------------------------------------------------------------
// Block attention: one warp per (b, h, block). BS=4, d=64. (unchanged, passing)
// ---------------------------------------------------------------------------
__global__ __launch_bounds__(256)
void block_attn_kernel(const float* __restrict__ qkv, float* __restrict__ o)
{
    const int gwarp = (blockIdx.x * blockDim.x + threadIdx.x) >> 5;
    const int lane  = threadIdx.x & 31;

    const int nb = gwarp & 1023;
    const int bh = gwarp >> 10;
    const int h  = bh & 15;
    const int b  = bh >> 4;
    const int l0 = nb * BLK;

    const size_t rowBase = ((size_t)(b * Ll + l0)) * NQKV + h * 192;

    float2 q[4], k[4], v[4];
#pragma unroll
    for (int i = 0; i < 4; ++i) {
        const float* p = qkv + rowBase + (size_t)i * NQKV + 2 * lane;
        q[i] = *(const float2*)(p);
        k[i] = *(const float2*)(p + 64);
        v[i] = *(const float2*)(p + 128);
    }

    float s[4][4];
#pragma unroll
    for (int i = 0; i < 4; ++i)
#pragma unroll
        for (int j = 0; j < 4; ++j)
            s[i][j] = fmaf(q[i].y, k[j].y, q[i].x * k[j].x);

#pragma unroll
    for (int i = 0; i < 4; ++i)
#pragma unroll
        for (int j = 0; j < 4; ++j)
#pragma unroll
            for (int off = 16; off > 0; off >>= 1)
                s[i][j] += __shfl_xor_sync(0xffffffffu, s[i][j], off);

    const float scale = 0.125f;
    float2 outv[4];
#pragma unroll
    for (int i = 0; i < 4; ++i) {
        float t0 = s[i][0] * scale, t1 = s[i][1] * scale;
        float t2 = s[i][2] * scale, t3 = s[i][3] * scale;
        float m = fmaxf(fmaxf(t0, t1), fmaxf(t2, t3));
        float e0 = __expf(t0 - m), e1 = __expf(t1 - m);
        float e2 = __expf(t2 - m), e3 = __expf(t3 - m);
        float inv = 1.0f / (e0 + e1 + e2 + e3);
        float p0 = e0 * inv, p1 = e1 * inv, p2 = e2 * inv, p3 = e3 * inv;
        float ox = p0 * v[0].x; ox = fmaf(p1, v[1].x, ox);
        ox = fmaf(p2, v[2].x, ox); ox = fmaf(p3, v[3].x, ox);
        float oy = p0 * v[0].y; oy = fmaf(p1, v[1].y, oy);
        oy = fmaf(p2, v[2].y, oy); oy = fmaf(p3, v[3].y, oy);
        outv[i].x = ox; outv[i].y = oy;
    }

    const size_t obase = ((size_t)(b * Ll + l0)) * Dd + h * HDIM + 2 * lane;
#pragma unroll
    for (int i = 0; i < 4; ++i)
        *(float2*)(o + obase + (size_t)i * Dd) = outv[i];
}

// ---------------------------------------------------------------------------
extern "C" void kernel_launch(void* const* d_in, const int* in_sizes, int n_in,
                              void* d_out, int out_size)
{
    const float* x     = (const float*)d_in[0];
    const float* Wqkv  = (const float*)d_in[1];
    const float* bqkv  = (const float*)d_in[2];
    const float* Wproj = (const float*)d_in[3];
    const float* bproj = (const float*)d_in[4];
    float* out = (float*)d_out;

    float* qkv = nullptr;
    float* ob  = nullptr;
    cudaGetSymbolAddress((void**)&qkv, g_qkv);
    cudaGetSymbolAddress((void**)&ob, g_o);

    cudaFuncSetAttribute(gemm_mma_kernel,
                         cudaFuncAttributeMaxDynamicSharedMemorySize, GEMM_SMEM);

    // 1) qkv = x @ W_qkv + b_qkv   (32768 x 3072 x 1024)
    {
        dim3 grid(NQKV / 256, MTOT / 128);
        gemm_mma_kernel<<<grid, 256, GEMM_SMEM>>>(x, Wqkv, bqkv, qkv, NQKV, Dd);
    }

    // 2) block attention
    {
        int nwarps = Bb * Hh * (Ll / BLK);
        block_attn_kernel<<<nwarps / 8, 256>>>(qkv, ob);
    }

    // 3) out = o @ W_proj + b_proj  (32768 x 1024 x 1024)
    {
        dim3 grid(Dd / 256, MTOT / 128);
        gemm_mma_kernel<<<grid, 256, GEMM_SMEM>>>(ob, Wproj, bproj, out, Dd, Dd);
    }
}

// round 4
// speedup vs baseline: 2.2966x; 1.0402x over previous
#include <cuda_runtime.h>
#include <cstdint>

// Problem constants
#define Bb     8
#define Ll     4096
#define Dd     1024
#define Hh     16
#define BLK    4
#define HDIM   64
#define MTOT   (Bb*Ll)        // 32768
#define NQKV   (3*Dd)         // 3072

// Scratch (no cudaMalloc allowed)
__device__ float g_qkv[100663296];  // 32768 * 3072   (f32 qkv)
__device__ float g_o[33554432];     // 32768 * 1024   (attention out, tf32-rounded)
__device__ float g_xt[33554432];    // x pre-rounded to tf32 bits
__device__ float g_wqt[3145728];    // W_qkv pre-rounded
__device__ float g_wpt[1048576];    // W_proj pre-rounded

// ---------------------------------------------------------------------------
// helpers
// ---------------------------------------------------------------------------
__device__ __forceinline__ uint32_t smem_u32(const void* p) {
    uint32_t a;
    asm("{ .reg .u64 t; cvta.to.shared.u64 t, %1; cvt.u32.u64 %0, t; }" : "=r"(a) : "l"(p));
    return a;
}

__device__ __forceinline__ float tf32r(float f) {
    uint32_t r;
    asm("cvt.rna.tf32.f32 %0, %1;" : "=r"(r) : "f"(f));
    return __uint_as_float(r);
}

__device__ __forceinline__ void cpasync16(uint32_t dst, const void* src) {
    asm volatile("cp.async.cg.shared.global [%0], [%1], 16;" :: "r"(dst), "l"(src));
}
#define CP_COMMIT() asm volatile("cp.async.commit_group;" ::: "memory")
#define CP_WAIT2()  asm volatile("cp.async.wait_group 2;" ::: "memory")

__device__ __forceinline__ void mma_tf32(float c[4], const uint32_t a[4], const uint32_t b[2]) {
    asm volatile(
        "mma.sync.aligned.m16n8k8.row.col.f32.tf32.tf32.f32 "
        "{%0,%1,%2,%3}, {%4,%5,%6,%7}, {%8,%9}, {%0,%1,%2,%3};\n"
        : "+f"(c[0]), "+f"(c[1]), "+f"(c[2]), "+f"(c[3])
        : "r"(a[0]), "r"(a[1]), "r"(a[2]), "r"(a[3]),
          "r"(b[0]), "r"(b[1]));
}

// ---------------------------------------------------------------------------
// Elementwise tf32 pre-round (float4 grid-stride)
// ---------------------------------------------------------------------------
__global__ __launch_bounds__(256)
void tf32_round_kernel(const float4* __restrict__ in, float4* __restrict__ out, int n4)
{
    int i = blockIdx.x * blockDim.x + threadIdx.x;
    int stride = gridDim.x * blockDim.x;
    for (; i < n4; i += stride) {
        float4 v = in[i];
        v.x = tf32r(v.x); v.y = tf32r(v.y);
        v.z = tf32r(v.z); v.w = tf32r(v.w);
        out[i] = v;
    }
}

// ---------------------------------------------------------------------------
// TF32 GEMM via mma.sync. CTA tile 128(M) x 256(N), BK=32, 512 threads,
// 16 warps of 64x32. Inputs are PRE-ROUNDED to tf32 bits (no in-loop cvt).
// A smem: K-major 128B rows, SW128 swizzle, ldmatrix.x4 (tf32-as-2xb16).
// B smem: K-major rows padded to 264 words (bank = 8k+n mod 32, conflict-free).
// 3-stage cp.async pipeline. Requires M%128==0, N%256==0, K%32==0.
// ---------------------------------------------------------------------------
#define A_STAGE 16384
#define B_ROWB  1056                 // 264 floats
#define B_STAGE (32 * B_ROWB)        // 33792
#define STAGES  3
#define GEMM_SMEM (STAGES * (A_STAGE + B_STAGE))   // 150528

__global__ __launch_bounds__(512, 1)
void gemm_mma_kernel(const float* __restrict__ A, const float* __restrict__ W,
                     const float* __restrict__ bias, float* __restrict__ C,
                     int N, int K)
{
    extern __shared__ char dsm[];
    const uint32_t sbase = smem_u32(dsm);

    uint32_t aSt[STAGES], bSt[STAGES];
#pragma unroll
    for (int s = 0; s < STAGES; ++s) {
        aSt[s] = sbase + s * A_STAGE;
        bSt[s] = sbase + STAGES * A_STAGE + s * B_STAGE;
    }

    const int tid  = threadIdx.x;
    const int wid  = tid >> 5;
    const int lane = tid & 31;
    const int warpM = wid & 1;       // 2 rows of 64
    const int warpN = wid >> 1;      // 8 cols of 32

    const int m0 = blockIdx.y * 128;
    const int n0 = blockIdx.x * 256;

    const float* Ag = A + (size_t)m0 * K;
    const float* Wg = W + n0;
    const int NC = K >> 5;

    float acc[4][4][4];
#pragma unroll
    for (int mt = 0; mt < 4; ++mt)
#pragma unroll
        for (int nt = 0; nt < 4; ++nt)
#pragma unroll
            for (int r = 0; r < 4; ++r) acc[mt][nt][r] = 0.0f;

    // ---- staging: chunk c -> stage s (512 threads) ----
    auto stage = [&](int c, int s) {
        const int k0 = c << 5;
        // A: 128 rows x 32 floats = 1024 16B-chunks
#pragma unroll
        for (int it = 0; it < 2; ++it) {
            int idx = tid + it * 512;
            int m = idx >> 3, k16 = idx & 7;
            cpasync16(aSt[s] + m * 128 + ((k16 ^ (m & 7)) << 4),
                      Ag + (size_t)m * K + k0 + k16 * 4);
        }
        // B: 32 rows x 256 floats = 2048 16B-chunks (padded rows)
#pragma unroll
        for (int it = 0; it < 4; ++it) {
            int idx = tid + it * 512;
            int k = idx >> 6, n16 = idx & 63;
            cpasync16(bSt[s] + k * B_ROWB + n16 * 16,
                      Wg + (size_t)(k0 + k) * N + n16 * 4);
        }
    };

    stage(0, 0); CP_COMMIT();
    stage(1, 1); CP_COMMIT();

    // A ldmatrix address pieces
    const int r8  = lane & 7;
    const int sel = lane >> 3;                 // 0..3
    const int rowAdd = r8 + ((sel & 2) << 2);  // +8 rows for mats 2,3
    const int colAdd = sel & 1;                // +1 16B-col for mats 1,3

    for (int c = 0; c < NC; ++c) {
        if (c + 2 < NC) stage(c + 2, (c + 2) % STAGES);
        CP_COMMIT();
        CP_WAIT2();
        __syncthreads();

        const uint32_t aB = aSt[c % STAGES];
        const uint32_t bB = bSt[c % STAGES];

#pragma unroll
        for (int ks = 0; ks < 4; ++ks) {
            // ---- A fragments: 4 m-tiles via ldmatrix.x4 ----
            uint32_t aF[4][4];
#pragma unroll
            for (int mt = 0; mt < 4; ++mt) {
                int row = warpM * 64 + mt * 16 + rowAdd;
                int col16 = 2 * ks + colAdd;
                uint32_t addr = aB + row * 128 + (((col16 ^ (row & 7)) << 4));
                uint32_t r0, r1, r2, r3;
                asm volatile("ldmatrix.sync.aligned.m8n8.x4.shared.b16 {%0,%1,%2,%3}, [%4];"
                             : "=r"(r0), "=r"(r1), "=r"(r2), "=r"(r3) : "r"(addr));
                aF[mt][0] = r0; aF[mt][1] = r2; aF[mt][2] = r1; aF[mt][3] = r3;
            }
            // ---- B fragments: 4 n-tiles, conflict-free LDS.32 ----
            uint32_t bF[4][2];
            const uint32_t bk = bB + (ks * 8 + (lane & 3)) * B_ROWB
                              + (warpN * 32 + (lane >> 2)) * 4;
#pragma unroll
            for (int nt = 0; nt < 4; ++nt) {
                asm volatile("ld.shared.b32 %0, [%1];" : "=r"(bF[nt][0]) : "r"(bk + nt * 32));
                asm volatile("ld.shared.b32 %0, [%1];" : "=r"(bF[nt][1]) : "r"(bk + nt * 32 + 4 * B_ROWB));
            }
            // ---- 16 MMAs ----
#pragma unroll
            for (int mt = 0; mt < 4; ++mt)
#pragma unroll
                for (int nt = 0; nt < 4; ++nt)
                    mma_tf32(acc[mt][nt], aF[mt], bF[nt]);
        }
        __syncthreads();
    }

    // ---- epilogue: bias + STG.64 ----
    const int col0 = n0 + warpN * 32 + 2 * (lane & 3);
    float2 bv[4];
#pragma unroll
    for (int nt = 0; nt < 4; ++nt)
        bv[nt] = *(const float2*)(bias + col0 + nt * 8);

    const int row0 = m0 + warpM * 64 + (lane >> 2);
#pragma unroll
    for (int mt = 0; mt < 4; ++mt) {
        int r = row0 + mt * 16;
#pragma unroll
        for (int nt = 0; nt < 4; ++nt) {
            int cn = col0 + nt * 8;
            float2 v0, v1;
            v0.x = acc[mt][nt][0] + bv[nt].x;
            v0.y = acc[mt][nt][1] + bv[nt].y;
            v1.x = acc[mt][nt][2] + bv[nt].x;
            v1.y = acc[mt][nt][3] + bv[nt].y;
            *(float2*)(C + (size_t)r * N + cn)       = v0;
            *(float2*)(C + (size_t)(r + 8) * N + cn) = v1;
        }
    }
}

// ---------------------------------------------------------------------------
// Block attention: one warp per (b, h, block). BS=4, d=64.
// Output is rounded to tf32 bits (feeds the proj GEMM directly).
// ---------------------------------------------------------------------------
__global__ __launch_bounds__(256)
void block_attn_kernel(const float* __restrict__ qkv, float* __restrict__ o)
{
    const int gwarp = (blockIdx.x * blockDim.x + threadIdx.x) >> 5;
    const int lane  = threadIdx.x & 31;

    const int nb = gwarp & 1023;
    const int bh = gwarp >> 10;
    const int h  = bh & 15;
    const int b  = bh >> 4;
    const int l0 = nb * BLK;

    const size_t rowBase = ((size_t)(b * Ll + l0)) * NQKV + h * 192;

    float2 q[4], k[4], v[4];
#pragma unroll
    for (int i = 0; i < 4; ++i) {
        const float* p = qkv + rowBase + (size_t)i * NQKV + 2 * lane;
        q[i] = *(const float2*)(p);
        k[i] = *(const float2*)(p + 64);
        v[i] = *(const float2*)(p + 128);
    }

    float s[4][4];
#pragma unroll
    for (int i = 0; i < 4; ++i)
#pragma unroll
        for (int j = 0; j < 4; ++j)
            s[i][j] = fmaf(q[i].y, k[j].y, q[i].x * k[j].x);

#pragma unroll
    for (int i = 0; i < 4; ++i)
#pragma unroll
        for (int j = 0; j < 4; ++j)
#pragma unroll
            for (int off = 16; off > 0; off >>= 1)
                s[i][j] += __shfl_xor_sync(0xffffffffu, s[i][j], off);

    const float scale = 0.125f;
    float2 outv[4];
#pragma unroll
    for (int i = 0; i < 4; ++i) {
        float t0 = s[i][0] * scale, t1 = s[i][1] * scale;
        float t2 = s[i][2] * scale, t3 = s[i][3] * scale;
        float m = fmaxf(fmaxf(t0, t1), fmaxf(t2, t3));
        float e0 = __expf(t0 - m), e1 = __expf(t1 - m);
        float e2 = __expf(t2 - m), e3 = __expf(t3 - m);
        float inv = 1.0f / (e0 + e1 + e2 + e3);
        float p0 = e0 * inv, p1 = e1 * inv, p2 = e2 * inv, p3 = e3 * inv;
        float ox = p0 * v[0].x; ox = fmaf(p1, v[1].x, ox);
        ox = fmaf(p2, v[2].x, ox); ox = fmaf(p3, v[3].x, ox);
        float oy = p0 * v[0].y; oy = fmaf(p1, v[1].y, oy);
        oy = fmaf(p2, v[2].y, oy); oy = fmaf(p3, v[3].y, oy);
        outv[i].x = tf32r(ox); outv[i].y = tf32r(oy);
    }

    const size_t obase = ((size_t)(b * Ll + l0)) * Dd + h * HDIM + 2 * lane;
#pragma unroll
    for (int i = 0; i < 4; ++i)
        *(float2*)(o + obase + (size_t)i * Dd) = outv[i];
}

// ---------------------------------------------------------------------------
extern "C" void kernel_launch(void* const* d_in, const int* in_sizes, int n_in,
                              void* d_out, int out_size)
{
    const float* x     = (const float*)d_in[0];
    const float* Wqkv  = (const float*)d_in[1];
    const float* bqkv  = (const float*)d_in[2];
    const float* Wproj = (const float*)d_in[3];
    const float* bproj = (const float*)d_in[4];
    float* out = (float*)d_out;

    float *qkv, *ob, *xt, *wqt, *wpt;
    cudaGetSymbolAddress((void**)&qkv, g_qkv);
    cudaGetSymbolAddress((void**)&ob,  g_o);
    cudaGetSymbolAddress((void**)&xt,  g_xt);
    cudaGetSymbolAddress((void**)&wqt, g_wqt);
    cudaGetSymbolAddress((void**)&wpt, g_wpt);

    cudaFuncSetAttribute(gemm_mma_kernel,
                         cudaFuncAttributeMaxDynamicSharedMemorySize, GEMM_SMEM);

    // 0) pre-round inputs/weights to tf32 bits
    tf32_round_kernel<<<8192, 256>>>((const float4*)x,     (float4*)xt,  MTOT * Dd / 4);
    tf32_round_kernel<<<3072, 256>>>((const float4*)Wqkv,  (float4*)wqt, Dd * NQKV / 4);
    tf32_round_kernel<<<1024, 256>>>((const float4*)Wproj, (float4*)wpt, Dd * Dd / 4);

    // 1) qkv = x @ W_qkv + b_qkv   (32768 x 3072 x 1024)
    {
        dim3 grid(NQKV / 256, MTOT / 128);
        gemm_mma_kernel<<<grid, 512, GEMM_SMEM>>>(xt, wqt, bqkv, qkv, NQKV, Dd);
    }

    // 2) block attention (writes tf32-rounded o)
    {
        int nwarps = Bb * Hh * (Ll / BLK);
        block_attn_kernel<<<nwarps / 8, 256>>>(qkv, ob);
    }

    // 3) out = o @ W_proj + b_proj  (32768 x 1024 x 1024)
    {
        dim3 grid(Dd / 256, MTOT / 128);
        gemm_mma_kernel<<<grid, 512, GEMM_SMEM>>>(ob, wpt, bproj, out, Dd, Dd);
    }
}